// round 9
// baseline (speedup 1.0000x reference)
#include <cuda_runtime.h>
#include <math.h>

#define D      128
#define BMAX   1024
#define SUB    2048
#define GRID   296          // 2 blocks/SM x 148 SMs: all resident (barrier-safe)

// Scratch: [0, BMAX*D) per-segment sums; [BMAX*D, +BMAX) counts (float).
// .bss => zero at load. Phase 2 re-zeroes exactly what it consumed, so the
// buffer is zero again before every graph replay.
__device__ float    g_buf[BMAX * D + BMAX];
__device__ unsigned g_bar;   // monotonic device-barrier ticket (never reset)

// softplus with the reference's Threshold(-50, 50) folding
__device__ __forceinline__ float softplus_thresh(float v) {
    float sp = fmaxf(v, 0.0f) + log1pf(expf(-fabsf(v)));
    return sp < 50.0f ? sp : -50.0f;
}

// ---------------------------------------------------------------------------
// ONE persistent kernel.
// Phase 1 (all 296 blocks): per-segment sum of (|x|+eps)^p + node counts over
//   a contiguous ~N/296 node span. 32 feature-quads (tx) x 8 node lanes (ty),
//   rolling pipeline (next 4 LDG.128 before current pow chain), .cs streaming.
//   Then blocks 0..255 pre-stage their W half-0 into smem (overlaps phase-1
//   stragglers). Device-wide ticket barrier.
// Phase 2 (blocks 0..255): gnp = s^(1/p) * n^(-qs0); out = gnp @ W^T + bias.
//   4 graph rows/block, two K=64 halves, stride-17 float4 pad, split
//   accumulator chains. Scratch re-zeroed inline.
// ---------------------------------------------------------------------------
__global__ void __launch_bounds__(256, 2)
fused_gnp(const float* __restrict__ x, const void* __restrict__ batch,
          const float* __restrict__ ps_raw, const float* __restrict__ qs_raw,
          const float* __restrict__ W, const float* __restrict__ bias,
          float* __restrict__ out, int N)
{
    __shared__ int   sseg[SUB];       // 8 KB
    __shared__ float w[128 * 68];     // 34.8 KB
    __shared__ float gs[4 * 128];     // 2 KB

    const int tid = threadIdx.x;
    const int tx  = tid & 31;   // feature quad: features [4*tx, 4*tx+3]
    const int ty  = tid >> 5;   // node lane 0..7
    const int bid = blockIdx.x;
    const unsigned G = gridDim.x;

    const long long lo = (long long)bid * N / (int)G;
    const long long hi = (long long)(bid + 1) * N / (int)G;

    // detect int32 vs int64 batch dtype (uniform across grid):
    // u64 at even idx ~N/4: int64 buffer -> small value; int32 -> >= 2^32
    const unsigned long long* p64b = (const unsigned long long*)batch;
    size_t qd = ((size_t)(N >> 2)) & ~(size_t)1;
    const bool is64 = (p64b[qd] < (1ull << 20));

    const float p = softplus_thresh(ps_raw[tx >> 4]);
    float* __restrict__ cntf = g_buf + BMAX * D;

    float ax = 0.f, ay = 0.f, az = 0.f, aw = 0.f;
    int cur = -1;
    int cnt = 0;

#define ACC4(v)                                   \
    ax += __powf(fabsf((v).x) + 1e-6f, p);        \
    ay += __powf(fabsf((v).y) + 1e-6f, p);        \
    az += __powf(fabsf((v).z) + 1e-6f, p);        \
    aw += __powf(fabsf((v).w) + 1e-6f, p);

#define FLUSH()                                                   \
    if (cnt > 0) {                                                \
        float* s = &g_buf[cur * D + tx * 4];                      \
        atomicAdd(s + 0, ax); atomicAdd(s + 1, ay);               \
        atomicAdd(s + 2, az); atomicAdd(s + 3, aw);               \
        if (tx == 0) atomicAdd(&cntf[cur], (float)cnt);           \
        ax = ay = az = aw = 0.f; cnt = 0;                         \
    }

#define PROC(v, b)                                \
    if ((b) != cur) { FLUSH(); cur = (b); }       \
    ACC4(v); cnt++;

    for (long long base = lo; base < hi; base += SUB) {
        const int len = (int)(hi - base < SUB ? hi - base : SUB);
        __syncthreads();             // protect sseg reuse across sub-chunks
        if (is64) {
            const long long* bb = (const long long*)batch;
            for (int i = tid; i < len; i += 256) sseg[i] = (int)bb[base + i];
        } else {
            const int* bb = (const int*)batch;
            for (int i = tid; i < len; i += 256) sseg[i] = bb[base + i];
        }
        __syncthreads();

        const float4* __restrict__ x4 = (const float4*)x + base * 32 + tx;

        int j = ty;
        bool have = (j + 24 < len);
        float4 v0, v1, v2, v3;
        if (have) {
            v0 = __ldcs(&x4[(size_t)(j)      * 32]);
            v1 = __ldcs(&x4[(size_t)(j + 8)  * 32]);
            v2 = __ldcs(&x4[(size_t)(j + 16) * 32]);
            v3 = __ldcs(&x4[(size_t)(j + 24) * 32]);
        }
        while (have) {
            const int jn = j + 32;
            const bool haven = (jn + 24 < len);
            float4 n0, n1, n2, n3;
            if (haven) {             // prefetch next iteration (MLP ~8)
                n0 = __ldcs(&x4[(size_t)(jn)      * 32]);
                n1 = __ldcs(&x4[(size_t)(jn + 8)  * 32]);
                n2 = __ldcs(&x4[(size_t)(jn + 16) * 32]);
                n3 = __ldcs(&x4[(size_t)(jn + 24) * 32]);
            }
            int b0s = sseg[j];
            int b3s = sseg[j + 24];
            if (b0s == cur && b3s == cur) {   // sorted: ends equal => all 4
                ACC4(v0); ACC4(v1); ACC4(v2); ACC4(v3);
                cnt += 4;
            } else {
                int b1s = sseg[j + 8];
                int b2s = sseg[j + 16];
                PROC(v0, b0s); PROC(v1, b1s); PROC(v2, b2s); PROC(v3, b3s);
            }
            v0 = n0; v1 = n1; v2 = n2; v3 = n3;
            j = jn; have = haven;
        }
        for (; j < len; j += 8) {            // tail
            float4 v = __ldcs(&x4[(size_t)j * 32]);
            int b = sseg[j];
            PROC(v, b);
        }
    }
    FLUSH();

#undef PROC
#undef FLUSH
#undef ACC4

    // ---- pre-stage W half-0 (overlaps other blocks' phase-1 tail) ----
    const float4* __restrict__ W4 = (const float4*)W;
    float4* w4 = (float4*)w;
    if (bid < 256) {
        for (int idx = tid; idx < 128 * 16; idx += 256) {
            int o2 = idx >> 4, dk4 = idx & 15;
            w4[o2 * 17 + dk4] = W4[o2 * 32 + dk4];        // cols 0..63
        }
    }
    __syncthreads();     // block done: all atomics issued, w half-0 staged

    // ---- device-wide ticket barrier (monotonic, replay-safe) ----
    if (tid == 0) {
        __threadfence();                         // release phase-1 writes
        unsigned old = atomicAdd(&g_bar, 1u);
        unsigned target = old - (old % G) + G;   // this replay's ticket goal
        while (*(volatile unsigned*)&g_bar < target) { __nanosleep(64); }
        __threadfence();                         // acquire
    }
    __syncthreads();

    if (bid >= 256) return;

    // ======================= phase 2: gnp + GEMM =======================
    const int o  = tid & 127;
    const int g  = tid >> 7;          // 0/1 -> rows {2g, 2g+1}
    const int b0 = bid * 4;

    const float qs0 = tanhf(qs_raw[0]);

    // gnp for 4 rows: 512 entries, 2 per thread; re-zero what we read
    // (thread-exclusive entries, block-exclusive rows).
    for (int idx = tid; idx < 512; idx += 256) {
        int r = idx >> 7, d = idx & 127;
        float pp = softplus_thresh(ps_raw[d >> 6]);
        float s = g_buf[(b0 + r) * D + d];
        g_buf[(b0 + r) * D + d] = 0.f;
        float n = cntf[b0 + r];
        gs[idx] = __powf(s, 1.0f / pp) * __powf(n, -qs0);
    }
    __syncthreads();                 // gs ready (w half-0 already staged)
    if (tid < 4) cntf[b0 + tid] = 0.f;   // after all cnt reads

    float a0 = bias[o], c0 = 0.f;    // row 2g   (split chains: 2x ILP)
    float a1 = bias[o], c1 = 0.f;    // row 2g+1

    const float4* gs4 = (const float4*)gs;

    #pragma unroll
    for (int dk4 = 0; dk4 < 16; dk4++) {         // half 0 (pre-staged)
        float4 wv = w4[o * 17 + dk4];
        float4 g0 = gs4[(g * 2)     * 32 + dk4];
        float4 g1 = gs4[(g * 2 + 1) * 32 + dk4];
        a0 += g0.x * wv.x; c0 += g0.z * wv.z;
        a0 += g0.y * wv.y; c0 += g0.w * wv.w;
        a1 += g1.x * wv.x; c1 += g1.z * wv.z;
        a1 += g1.y * wv.y; c1 += g1.w * wv.w;
    }

    __syncthreads();                 // half-0 reads done before restage
    for (int idx = tid; idx < 128 * 16; idx += 256) {
        int o2 = idx >> 4, dk4 = idx & 15;
        w4[o2 * 17 + dk4] = W4[o2 * 32 + 16 + dk4];       // cols 64..127
    }
    __syncthreads();

    #pragma unroll
    for (int dk4 = 0; dk4 < 16; dk4++) {         // half 1
        float4 wv = w4[o * 17 + dk4];
        int d4 = 16 + dk4;
        float4 g0 = gs4[(g * 2)     * 32 + d4];
        float4 g1 = gs4[(g * 2 + 1) * 32 + d4];
        a0 += g0.x * wv.x; c0 += g0.z * wv.z;
        a0 += g0.y * wv.y; c0 += g0.w * wv.w;
        a1 += g1.x * wv.x; c1 += g1.z * wv.z;
        a1 += g1.y * wv.y; c1 += g1.w * wv.w;
    }

    out[(size_t)(b0 + g * 2)     * D + o] = a0 + c0;
    out[(size_t)(b0 + g * 2 + 1) * D + o] = a1 + c1;
}

// ---------------------------------------------------------------------------
extern "C" void kernel_launch(void* const* d_in, const int* in_sizes, int n_in,
                              void* d_out, int out_size)
{
    const float* x      = (const float*)d_in[0];
    const void*  batch  = d_in[1];
    const float* ps_raw = (const float*)d_in[2];
    const float* qs_raw = (const float*)d_in[3];
    const float* W      = (const float*)d_in[4];
    const float* bias   = (const float*)d_in[5];
    float*       out    = (float*)d_out;

    const int N = in_sizes[0] / D;    // node count from x (dtype-proof)

    fused_gnp<<<GRID, 256>>>(x, batch, ps_raw, qs_raw, W, bias, out, N);
}

// round 10
// speedup vs baseline: 1.1025x; 1.1025x over previous
#include <cuda_runtime.h>
#include <math.h>

#define D     128
#define BMAX  1024
#define SUB   2048
#define NTILE 256        // phase-2 tiles: 1024 graphs / 4 rows

// Scratch: [0, BMAX*D) per-segment sums; [BMAX*D, +BMAX) counts (float).
// .bss => zero at load. Phase 2 re-zeroes exactly what it consumed, so the
// buffer is zero again before every graph replay.
__device__ float    g_buf[BMAX * D + BMAX];
__device__ unsigned g_bar;   // monotonic device-barrier ticket (never reset)

// softplus with the reference's Threshold(-50, 50) folding
__device__ __forceinline__ float softplus_thresh(float v) {
    float sp = fmaxf(v, 0.0f) + log1pf(expf(-fabsf(v)));
    return sp < 50.0f ? sp : -50.0f;
}

// ---------------------------------------------------------------------------
// ONE persistent kernel, tiny smem (10KB) so phase-1 keeps 3 blocks/SM.
// Phase 1: per-segment sum of (|x|+eps)^p + node counts over a contiguous
//   ~N/G span. 32 feature-quads (tx) x 8 node lanes (ty); rolling pipeline
//   (next 4 LDG.128 issued before current pow chain); .cs streaming.
// Device-wide monotonic ticket barrier (grid sized to guaranteed residency).
// Phase 2: gnp = s^(1/p) * n^(-qs0); out = gnp @ W^T + bias via
//   warp-shuffle GEMM: gs in registers, W read with coalesced LDG.128,
//   4 dot-products reduced by shfl. No W smem tile.
// ---------------------------------------------------------------------------
__global__ void __launch_bounds__(256, 3)
fused_gnp(const float* __restrict__ x, const void* __restrict__ batch,
          const float* __restrict__ ps_raw, const float* __restrict__ qs_raw,
          const float* __restrict__ W, const float* __restrict__ bias,
          float* __restrict__ out, int N)
{
    __shared__ int   sseg[SUB];       // 8 KB
    __shared__ float gs[4 * 128];     // 2 KB

    const int tid = threadIdx.x;
    const int tx  = tid & 31;   // feature quad: features [4*tx, 4*tx+3]
    const int ty  = tid >> 5;   // node lane 0..7
    const int bid = blockIdx.x;
    const unsigned G = gridDim.x;

    const long long lo = (long long)bid * N / (int)G;
    const long long hi = (long long)(bid + 1) * N / (int)G;

    // detect int32 vs int64 batch dtype (uniform across grid):
    // u64 at even idx ~N/4: int64 buffer -> small value; int32 -> >= 2^32
    const unsigned long long* p64b = (const unsigned long long*)batch;
    size_t qd = ((size_t)(N >> 2)) & ~(size_t)1;
    const bool is64 = (p64b[qd] < (1ull << 20));

    const float p = softplus_thresh(ps_raw[tx >> 4]);
    float* __restrict__ cntf = g_buf + BMAX * D;

    float ax = 0.f, ay = 0.f, az = 0.f, aw = 0.f;
    int cur = -1;
    int cnt = 0;

#define ACC4(v)                                   \
    ax += __powf(fabsf((v).x) + 1e-6f, p);        \
    ay += __powf(fabsf((v).y) + 1e-6f, p);        \
    az += __powf(fabsf((v).z) + 1e-6f, p);        \
    aw += __powf(fabsf((v).w) + 1e-6f, p);

#define FLUSH()                                                   \
    if (cnt > 0) {                                                \
        float* s = &g_buf[cur * D + tx * 4];                      \
        atomicAdd(s + 0, ax); atomicAdd(s + 1, ay);               \
        atomicAdd(s + 2, az); atomicAdd(s + 3, aw);               \
        if (tx == 0) atomicAdd(&cntf[cur], (float)cnt);           \
        ax = ay = az = aw = 0.f; cnt = 0;                         \
    }

#define PROC(v, b)                                \
    if ((b) != cur) { FLUSH(); cur = (b); }       \
    ACC4(v); cnt++;

    for (long long base = lo; base < hi; base += SUB) {
        const int len = (int)(hi - base < SUB ? hi - base : SUB);
        __syncthreads();             // protect sseg reuse across sub-chunks
        if (is64) {
            const long long* bb = (const long long*)batch;
            for (int i = tid; i < len; i += 256) sseg[i] = (int)bb[base + i];
        } else {
            const int* bb = (const int*)batch;
            for (int i = tid; i < len; i += 256) sseg[i] = bb[base + i];
        }
        __syncthreads();

        const float4* __restrict__ x4 = (const float4*)x + base * 32 + tx;

        int j = ty;
        bool have = (j + 24 < len);
        float4 v0, v1, v2, v3;
        if (have) {
            v0 = __ldcs(&x4[(size_t)(j)      * 32]);
            v1 = __ldcs(&x4[(size_t)(j + 8)  * 32]);
            v2 = __ldcs(&x4[(size_t)(j + 16) * 32]);
            v3 = __ldcs(&x4[(size_t)(j + 24) * 32]);
        }
        while (have) {
            const int jn = j + 32;
            const bool haven = (jn + 24 < len);
            float4 n0, n1, n2, n3;
            if (haven) {             // prefetch next iteration (MLP ~8)
                n0 = __ldcs(&x4[(size_t)(jn)      * 32]);
                n1 = __ldcs(&x4[(size_t)(jn + 8)  * 32]);
                n2 = __ldcs(&x4[(size_t)(jn + 16) * 32]);
                n3 = __ldcs(&x4[(size_t)(jn + 24) * 32]);
            }
            int b0s = sseg[j];
            int b3s = sseg[j + 24];
            if (b0s == cur && b3s == cur) {   // sorted: ends equal => all 4
                ACC4(v0); ACC4(v1); ACC4(v2); ACC4(v3);
                cnt += 4;
            } else {
                int b1s = sseg[j + 8];
                int b2s = sseg[j + 16];
                PROC(v0, b0s); PROC(v1, b1s); PROC(v2, b2s); PROC(v3, b3s);
            }
            v0 = n0; v1 = n1; v2 = n2; v3 = n3;
            j = jn; have = haven;
        }
        for (; j < len; j += 8) {            // tail
            float4 v = __ldcs(&x4[(size_t)j * 32]);
            int b = sseg[j];
            PROC(v, b);
        }
    }
    FLUSH();

#undef PROC
#undef FLUSH
#undef ACC4

    __syncthreads();     // block done: all phase-1 atomics issued

    // ---- device-wide ticket barrier (monotonic, replay-safe) ----
    if (tid == 0) {
        __threadfence();                         // release phase-1 writes
        unsigned old = atomicAdd(&g_bar, 1u);
        if (bid < NTILE) {                       // only phase-2 blocks wait
            unsigned target = old - (old % G) + G;
            while (*(volatile unsigned*)&g_bar < target) { __nanosleep(64); }
            __threadfence();                     // acquire
        }
    }
    __syncthreads();
    if (bid >= NTILE) return;

    // ======================= phase 2: gnp + GEMM =======================
    const int wi = tid >> 5;          // warp 0..7
    const int l  = tid & 31;          // lane
    const float qs0 = tanhf(qs_raw[0]);
    const float4* __restrict__ W4  = (const float4*)W;
    const float4* gs4 = (const float4*)gs;

    for (int tile = bid; tile < NTILE; tile += (int)G) {
        const int b0 = tile * 4;

        __syncthreads();             // protect gs reuse across tiles
        // gnp for 4 rows: 512 entries, 2 per thread; re-zero what we read
        // (thread-exclusive entries, block-exclusive rows).
        for (int idx = tid; idx < 512; idx += 256) {
            int r = idx >> 7, d = idx & 127;
            float pp = softplus_thresh(ps_raw[d >> 6]);
            float s = g_buf[(b0 + r) * D + d];
            g_buf[(b0 + r) * D + d] = 0.f;
            float n = cntf[b0 + r];
            gs[idx] = __powf(s, 1.0f / pp) * __powf(n, -qs0);
        }
        __syncthreads();
        if (tid < 4) cntf[b0 + tid] = 0.f;   // after all cnt reads

        // lane l holds gs[d=4l..4l+3] for all 4 rows (registers)
        float4 G0 = gs4[0 * 32 + l];
        float4 G1 = gs4[1 * 32 + l];
        float4 G2 = gs4[2 * 32 + l];
        float4 G3 = gs4[3 * 32 + l];

        #pragma unroll
        for (int oo = 0; oo < 16; oo++) {
            int o = oo * 8 + wi;                 // warp covers W row o
            float4 wv = W4[o * 32 + l];          // coalesced 512B per warp
            float p0 = wv.x * G0.x + wv.y * G0.y + wv.z * G0.z + wv.w * G0.w;
            float p1 = wv.x * G1.x + wv.y * G1.y + wv.z * G1.z + wv.w * G1.w;
            float p2 = wv.x * G2.x + wv.y * G2.y + wv.z * G2.z + wv.w * G2.w;
            float p3 = wv.x * G3.x + wv.y * G3.y + wv.z * G3.z + wv.w * G3.w;
            #pragma unroll
            for (int s = 16; s > 0; s >>= 1) {
                p0 += __shfl_xor_sync(0xffffffffu, p0, s);
                p1 += __shfl_xor_sync(0xffffffffu, p1, s);
                p2 += __shfl_xor_sync(0xffffffffu, p2, s);
                p3 += __shfl_xor_sync(0xffffffffu, p3, s);
            }
            if (l == 0) {
                float bo = bias[o];
                out[(size_t)(b0 + 0) * D + o] = p0 + bo;
                out[(size_t)(b0 + 1) * D + o] = p1 + bo;
                out[(size_t)(b0 + 2) * D + o] = p2 + bo;
                out[(size_t)(b0 + 3) * D + o] = p3 + bo;
            }
        }
    }
}

// ---------------------------------------------------------------------------
extern "C" void kernel_launch(void* const* d_in, const int* in_sizes, int n_in,
                              void* d_out, int out_size)
{
    const float* x      = (const float*)d_in[0];
    const void*  batch  = d_in[1];
    const float* ps_raw = (const float*)d_in[2];
    const float* qs_raw = (const float*)d_in[3];
    const float* W      = (const float*)d_in[4];
    const float* bias   = (const float*)d_in[5];
    float*       out    = (float*)d_out;

    const int N = in_sizes[0] / D;    // node count from x (dtype-proof)

    // grid = guaranteed-resident block count (barrier deadlock-safe)
    int nsm = 148, nb = 1;
    cudaDeviceGetAttribute(&nsm, cudaDevAttrMultiProcessorCount, 0);
    cudaOccupancyMaxActiveBlocksPerMultiprocessor(&nb, fused_gnp, 256, 0);
    if (nb < 1) nb = 1;
    int grid = nb * nsm;

    fused_gnp<<<grid, 256>>>(x, batch, ps_raw, qs_raw, W, bias, out, N);
}

// round 11
// speedup vs baseline: 1.1050x; 1.0023x over previous
#include <cuda_runtime.h>
#include <math.h>

#define D     128
#define BMAX  1024
#define SUB   2048
#define NTILE 256        // phase-2 tiles: 1024 graphs / 4 rows

// Scratch: [0, BMAX*D) per-segment sums; [BMAX*D, +BMAX) counts (float).
// .bss => zero at load. Phase 2 re-zeroes exactly what it consumed, so the
// buffer is zero again before every graph replay.
__device__ float    g_buf[BMAX * D + BMAX];
__device__ unsigned g_bar;   // monotonic device-barrier ticket (never reset)

// softplus with the reference's Threshold(-50, 50) folding
__device__ __forceinline__ float softplus_thresh(float v) {
    float sp = fmaxf(v, 0.0f) + log1pf(expf(-fabsf(v)));
    return sp < 50.0f ? sp : -50.0f;
}

// ---------------------------------------------------------------------------
// ONE persistent kernel, tiny smem (10KB), 64 regs (launch_bounds 256x4)
// => 4 blocks/SM, 32 warps/SM.
// Phase 1: per-segment sum of (|x|+eps)^p + node counts over a contiguous
//   ~N/G span. 32 feature-quads (tx) x 8 node lanes (ty); rolling pipeline
//   (next 4 LDG.128 issued before current pow chain); .cs streaming;
//   strength-reduced pointers (no per-load 64-bit IMAD).
// Device-wide monotonic ticket barrier (grid = guaranteed residency).
// Phase 2: gnp = s^(1/p) * n^(-qs0); out = gnp @ W^T + bias via
//   warp-shuffle GEMM (gs in registers, coalesced W LDG.128, shfl reduce).
// ---------------------------------------------------------------------------
__global__ void __launch_bounds__(256, 4)
fused_gnp(const float* __restrict__ x, const void* __restrict__ batch,
          const float* __restrict__ ps_raw, const float* __restrict__ qs_raw,
          const float* __restrict__ W, const float* __restrict__ bias,
          float* __restrict__ out, int N)
{
    __shared__ int   sseg[SUB];       // 8 KB
    __shared__ float gs[4 * 128];     // 2 KB

    const int tid = threadIdx.x;
    const int tx  = tid & 31;   // feature quad: features [4*tx, 4*tx+3]
    const int ty  = tid >> 5;   // node lane 0..7
    const int bid = blockIdx.x;
    const unsigned G = gridDim.x;

    const long long lo = (long long)bid * N / (int)G;
    const long long hi = (long long)(bid + 1) * N / (int)G;

    // detect int32 vs int64 batch dtype (uniform across grid):
    // u64 at even idx ~N/4: int64 buffer -> small value; int32 -> >= 2^32
    const unsigned long long* p64b = (const unsigned long long*)batch;
    size_t qd = ((size_t)(N >> 2)) & ~(size_t)1;
    const bool is64 = (p64b[qd] < (1ull << 20));

    const float p = softplus_thresh(ps_raw[tx >> 4]);
    float* __restrict__ cntf = g_buf + BMAX * D;

    float ax = 0.f, ay = 0.f, az = 0.f, aw = 0.f;
    int cur = -1;
    int cnt = 0;

#define ACC4(v)                                   \
    ax += __powf(fabsf((v).x) + 1e-6f, p);        \
    ay += __powf(fabsf((v).y) + 1e-6f, p);        \
    az += __powf(fabsf((v).z) + 1e-6f, p);        \
    aw += __powf(fabsf((v).w) + 1e-6f, p);

#define FLUSH()                                                   \
    if (cnt > 0) {                                                \
        float* s = &g_buf[cur * D + tx * 4];                      \
        atomicAdd(s + 0, ax); atomicAdd(s + 1, ay);               \
        atomicAdd(s + 2, az); atomicAdd(s + 3, aw);               \
        if (tx == 0) atomicAdd(&cntf[cur], (float)cnt);           \
        ax = ay = az = aw = 0.f; cnt = 0;                         \
    }

#define PROC(v, b)                                \
    if ((b) != cur) { FLUSH(); cur = (b); }       \
    ACC4(v); cnt++;

    for (long long base = lo; base < hi; base += SUB) {
        const int len = (int)(hi - base < SUB ? hi - base : SUB);
        __syncthreads();             // protect sseg reuse across sub-chunks
        if (is64) {
            const long long* bb = (const long long*)batch;
            for (int i = tid; i < len; i += 256) sseg[i] = (int)bb[base + i];
        } else {
            const int* bb = (const int*)batch;
            for (int i = tid; i < len; i += 256) sseg[i] = bb[base + i];
        }
        __syncthreads();

        // strength-reduced: one pointer, constant stride of 32*8 float4/iter
        const float4* __restrict__ xp =
            (const float4*)x + base * 32 + tx + (size_t)ty * 32;

        int j = ty;
        bool have = (j + 24 < len);
        float4 v0, v1, v2, v3;
        if (have) {
            v0 = __ldcs(xp);
            v1 = __ldcs(xp + 8 * 32);
            v2 = __ldcs(xp + 16 * 32);
            v3 = __ldcs(xp + 24 * 32);
        }
        while (have) {
            const int jn = j + 32;
            const bool haven = (jn + 24 < len);
            const float4* xpn = xp + 32 * 32;
            float4 n0, n1, n2, n3;
            if (haven) {             // prefetch next iteration (MLP ~8)
                n0 = __ldcs(xpn);
                n1 = __ldcs(xpn + 8 * 32);
                n2 = __ldcs(xpn + 16 * 32);
                n3 = __ldcs(xpn + 24 * 32);
            }
            int b0s = sseg[j];
            int b3s = sseg[j + 24];
            if (b0s == cur && b3s == cur) {   // sorted: ends equal => all 4
                ACC4(v0); ACC4(v1); ACC4(v2); ACC4(v3);
                cnt += 4;
            } else {
                int b1s = sseg[j + 8];
                int b2s = sseg[j + 16];
                PROC(v0, b0s); PROC(v1, b1s); PROC(v2, b2s); PROC(v3, b3s);
            }
            v0 = n0; v1 = n1; v2 = n2; v3 = n3;
            xp = xpn;
            j = jn; have = haven;
        }
        for (; j < len; j += 8) {            // tail
            float4 v = __ldcs(xp);
            int b = sseg[j];
            PROC(v, b);
            xp += 8 * 32;
        }
    }
    FLUSH();

#undef PROC
#undef FLUSH
#undef ACC4

    __syncthreads();     // block done: all phase-1 atomics issued

    // ---- device-wide ticket barrier (monotonic, replay-safe) ----
    if (tid == 0) {
        __threadfence();                         // release phase-1 writes
        unsigned old = atomicAdd(&g_bar, 1u);
        if (bid < NTILE) {                       // only phase-2 blocks wait
            unsigned target = old - (old % G) + G;
            while (*(volatile unsigned*)&g_bar < target) { __nanosleep(64); }
            __threadfence();                     // acquire
        }
    }
    __syncthreads();
    if (bid >= NTILE) return;

    // ======================= phase 2: gnp + GEMM =======================
    const int wi = tid >> 5;          // warp 0..7
    const int l  = tid & 31;          // lane
    const float qs0 = tanhf(qs_raw[0]);
    const float4* __restrict__ W4  = (const float4*)W;
    const float4* gs4 = (const float4*)gs;

    for (int tile = bid; tile < NTILE; tile += (int)G) {
        const int b0 = tile * 4;

        __syncthreads();             // protect gs reuse across tiles
        // gnp for 4 rows: 512 entries, 2 per thread; re-zero what we read
        // (thread-exclusive entries, block-exclusive rows).
        for (int idx = tid; idx < 512; idx += 256) {
            int r = idx >> 7, d = idx & 127;
            float pp = softplus_thresh(ps_raw[d >> 6]);
            float s = g_buf[(b0 + r) * D + d];
            g_buf[(b0 + r) * D + d] = 0.f;
            float n = cntf[b0 + r];
            gs[idx] = __powf(s, 1.0f / pp) * __powf(n, -qs0);
        }
        __syncthreads();
        if (tid < 4) cntf[b0 + tid] = 0.f;   // after all cnt reads

        // lane l holds gs[d=4l..4l+3] for all 4 rows (registers)
        float4 G0 = gs4[0 * 32 + l];
        float4 G1 = gs4[1 * 32 + l];
        float4 G2 = gs4[2 * 32 + l];
        float4 G3 = gs4[3 * 32 + l];

        #pragma unroll 4
        for (int oo = 0; oo < 16; oo++) {
            int o = oo * 8 + wi;                 // warp covers W row o
            float4 wv = W4[o * 32 + l];          // coalesced 512B per warp
            float p0 = wv.x * G0.x + wv.y * G0.y + wv.z * G0.z + wv.w * G0.w;
            float p1 = wv.x * G1.x + wv.y * G1.y + wv.z * G1.z + wv.w * G1.w;
            float p2 = wv.x * G2.x + wv.y * G2.y + wv.z * G2.z + wv.w * G2.w;
            float p3 = wv.x * G3.x + wv.y * G3.y + wv.z * G3.z + wv.w * G3.w;
            #pragma unroll
            for (int s = 16; s > 0; s >>= 1) {
                p0 += __shfl_xor_sync(0xffffffffu, p0, s);
                p1 += __shfl_xor_sync(0xffffffffu, p1, s);
                p2 += __shfl_xor_sync(0xffffffffu, p2, s);
                p3 += __shfl_xor_sync(0xffffffffu, p3, s);
            }
            if (l == 0) {
                float bo = bias[o];
                out[(size_t)(b0 + 0) * D + o] = p0 + bo;
                out[(size_t)(b0 + 1) * D + o] = p1 + bo;
                out[(size_t)(b0 + 2) * D + o] = p2 + bo;
                out[(size_t)(b0 + 3) * D + o] = p3 + bo;
            }
        }
    }
}

// ---------------------------------------------------------------------------
extern "C" void kernel_launch(void* const* d_in, const int* in_sizes, int n_in,
                              void* d_out, int out_size)
{
    const float* x      = (const float*)d_in[0];
    const void*  batch  = d_in[1];
    const float* ps_raw = (const float*)d_in[2];
    const float* qs_raw = (const float*)d_in[3];
    const float* W      = (const float*)d_in[4];
    const float* bias   = (const float*)d_in[5];
    float*       out    = (float*)d_out;

    const int N = in_sizes[0] / D;    // node count from x (dtype-proof)

    // grid = guaranteed-resident block count (barrier deadlock-safe)
    int nsm = 148, nb = 1;
    cudaDeviceGetAttribute(&nsm, cudaDevAttrMultiProcessorCount, 0);
    cudaOccupancyMaxActiveBlocksPerMultiprocessor(&nb, fused_gnp, 256, 0);
    if (nb < 1) nb = 1;
    int grid = nb * nsm;

    fused_gnp<<<grid, 256>>>(x, batch, ps_raw, qs_raw, W, bias, out, N);
}